// round 14
// baseline (speedup 1.0000x reference)
#include <cuda_runtime.h>
#include <math.h>

#define BB 4
#define NN 4096
#define DD 8
#define KK 64               /* instance ids */
#define CC1 16              /* pass1 chunks per batch */
#define CH1 256             /* pass1 threads */
#define CC2 16              /* pass2 chunks per batch */
#define CH2 256             /* pass2 threads */
#define JT 128              /* j per rep tile (64 packed pairs) */
#define IT 256              /* i per rep tile (2 per thread) */
#define GI (NN / IT)        /* 16 */
#define GJ (NN / JT)        /* 32 */
#define TR 128              /* k_rep threads */
#define SLOTS 64            /* rep scatter slots */

#define LOG2E  1.4426950408889634f
#define SCALE  1.6986436f   /* sqrt(2*log2(e)) */

typedef unsigned long long ull;

// ---------------- scratch (no allocations; zero-init valid) ----------------
__device__ float g_cp_emb[BB][NN][DD];   // compacted CP embeddings, pre-scaled by SCALE
__device__ float g_nsq   [BB][NN];       // -|e_raw|^2 * log2(e)
__device__ int   g_pos     [BB];
__device__ int   g_cnt     [BB][KK];
__device__ int   g_firstmax[BB][KK];     // max(NN - i); 0 = no CP
__device__ float g_bce1    [BB];
__device__ float g_bce0    [BB];
__device__ float g_seg     [BB][KK];
__device__ float g_rep_parts[BB][SLOTS]; // scattered repulsion partials

__device__ __forceinline__ float ex2f(float x) {
    float r; asm("ex2.approx.ftz.f32 %0, %1;" : "=f"(r) : "f"(x)); return r;
}
__device__ __forceinline__ float softplus_f(float x) {
    return fmaxf(x, 0.f) + log1pf(expf(-fabsf(x)));
}
__device__ __forceinline__ ull ffma2(ull a, ull b, ull c) {
    ull d; asm("fma.rn.f32x2 %0, %1, %2, %3;" : "=l"(d) : "l"(a), "l"(b), "l"(c));
    return d;
}
__device__ __forceinline__ ull addx2(ull a, ull b) {
    ull d; asm("add.rn.f32x2 %0, %1, %2;" : "=l"(d) : "l"(a), "l"(b));
    return d;
}
__device__ __forceinline__ ull packx2(float lo, float hi) {
    ull d; asm("mov.b64 %0, {%1, %2};" : "=l"(d) : "f"(lo), "f"(hi));
    return d;
}
__device__ __forceinline__ void unpackx2(float& lo, float& hi, ull v) {
    asm("mov.b64 {%0, %1}, %2;" : "=f"(lo), "=f"(hi) : "l"(v));
}

// ============ kernel 1: counts, first-CP, BCE, scaled CP compaction ============
__global__ void __launch_bounds__(CH1) k_pass1(const float* __restrict__ beta,
                                               const float* __restrict__ embed,
                                               const int*   __restrict__ sid,
                                               const int*   __restrict__ iscp)
{
    const int c   = blockIdx.x;
    const int b   = blockIdx.y;
    const int tid = threadIdx.x;
    const int i   = c * CH1 + tid;
    const int g   = b * NN + i;
    const int lane = tid & 31;
    const int wrp  = tid >> 5;

    __shared__ int   s_cnt[KK];
    __shared__ int   s_first[KK];
    __shared__ float s_w1[CH1 / 32];
    __shared__ float s_w0[CH1 / 32];
    __shared__ int   s_wcnt[CH1 / 32];
    __shared__ int   s_base;

    if (tid < KK) { s_cnt[tid] = 0; s_first[tid] = NN; }
    __syncthreads();

    const int   s  = sid[g];
    const int   cp = iscp[g];
    const float bt = beta[g];

    atomicAdd(&s_cnt[s], 1);
    float l1 = 0.f, l0 = 0.f;
    if (cp == 1) { atomicMin(&s_first[s], i); l1 = softplus_f(-bt); }
    else         { l0 = softplus_f(bt); }

    // block-aggregated compaction ticket: ONE global atomic per block
    const unsigned bal = __ballot_sync(0xffffffffu, cp == 1);
    if (lane == 0) s_wcnt[wrp] = __popc(bal);
    __syncthreads();
    if (tid == 0) {
        int tot = 0;
        #pragma unroll
        for (int w = 0; w < CH1 / 32; w++) tot += s_wcnt[w];
        s_base = atomicAdd(&g_pos[b], tot);
    }
    __syncthreads();
    if (cp == 1) {
        int wb = s_base;
        #pragma unroll
        for (int w = 0; w < CH1 / 32; w++) if (w < wrp) wb += s_wcnt[w];
        const int w = wb + __popc(bal & ((1u << lane) - 1u));
        const float4* e = (const float4*)&embed[(size_t)g * DD];
        float4 a = e[0], d = e[1];
        float sq = a.x*a.x + a.y*a.y + a.z*a.z + a.w*a.w
                 + d.x*d.x + d.y*d.y + d.z*d.z + d.w*d.w;
        *(float4*)&g_cp_emb[b][w][0] = make_float4(a.x*SCALE, a.y*SCALE, a.z*SCALE, a.w*SCALE);
        *(float4*)&g_cp_emb[b][w][4] = make_float4(d.x*SCALE, d.y*SCALE, d.z*SCALE, d.w*SCALE);
        g_nsq[b][w] = -sq * LOG2E;
    }

    #pragma unroll
    for (int off = 16; off; off >>= 1) {
        l1 += __shfl_down_sync(0xffffffffu, l1, off);
        l0 += __shfl_down_sync(0xffffffffu, l0, off);
    }
    if (lane == 0) { s_w1[wrp] = l1; s_w0[wrp] = l0; }
    __syncthreads();

    if (tid < KK) {
        if (s_cnt[tid] > 0)    atomicAdd(&g_cnt[b][tid], s_cnt[tid]);
        if (s_first[tid] < NN) atomicMax(&g_firstmax[b][tid], NN - s_first[tid]);
    }
    if (tid == 0) {
        float S1 = 0.f, S0 = 0.f;
        #pragma unroll
        for (int w = 0; w < CH1 / 32; w++) { S1 += s_w1[w]; S0 += s_w0[w]; }
        atomicAdd(&g_bce1[b], S1);
        atomicAdd(&g_bce0[b], S0);
    }
}

// ============ kernel 2: attraction segment sums (static grid, no finalize) ============
__global__ void __launch_bounds__(CH2) k_pass2(const float* __restrict__ embed,
                                               const int*   __restrict__ sid)
{
    const int c   = blockIdx.x;
    const int b   = blockIdx.y;
    const int tid = threadIdx.x;

    __shared__ int   s_f[KK];
    __shared__ float s_cpe[KK][DD];
    __shared__ float s_seg[KK];

    if (tid < KK) {
        int m = g_firstmax[b][tid];
        s_f[tid]   = m;
        s_seg[tid] = 0.f;
        if (m > 0) {
            int f = NN - m;
            const float4* e = (const float4*)&embed[((size_t)b * NN + f) * DD];
            *(float4*)&s_cpe[tid][0] = e[0];
            *(float4*)&s_cpe[tid][4] = e[1];
        }
    }
    __syncthreads();

    const int i = c * CH2 + tid;
    const int g = b * NN + i;
    const int s = sid[g];
    if (s_f[s] > 0) {
        const float4* e = (const float4*)&embed[(size_t)g * DD];
        float4 a = e[0], d = e[1];
        float x0 = a.x - s_cpe[s][0], x1 = a.y - s_cpe[s][1];
        float x2 = a.z - s_cpe[s][2], x3 = a.w - s_cpe[s][3];
        float x4 = d.x - s_cpe[s][4], x5 = d.y - s_cpe[s][5];
        float x6 = d.z - s_cpe[s][6], x7 = d.w - s_cpe[s][7];
        float d2 = x0*x0 + x1*x1 + x2*x2 + x3*x3 + x4*x4 + x5*x5 + x6*x6 + x7*x7;
        atomicAdd(&s_seg[s], d2);
    }
    __syncthreads();
    if (tid < KK && s_seg[tid] != 0.f) atomicAdd(&g_seg[b][tid], s_seg[tid]);
}

// ============ kernel 3: STATIC tiled repulsion (256i x 128j), packed f32x2 ============
__global__ void __launch_bounds__(TR) k_rep()
{
    const int ti = blockIdx.x;              // 0..GI-1
    const int tj = blockIdx.y;              // 0..GJ-1
    if (tj < 2 * ti) return;                // no j > i possible below band
    const int b  = blockIdx.z;
    const int P  = g_pos[b];
    const int i0 = ti * IT;
    const int j0 = tj * JT;
    if (i0 >= P || j0 >= P) return;

    __shared__ __align__(16) ull sJ[JT/2][10];   // packed j-pair rows (80B each)
    __shared__ float s_wsum[4];

    const int t    = threadIdx.x;
    const int lane = t & 31;
    const int jn   = min(JT, P - j0);

    // pack 64 j-pair rows into smem (from row-major global)
    if (t < JT / 2) {
        const int j0g = j0 + 2 * t;
        const int j1g = j0g + 1;
        float4 a0 = *(const float4*)&g_cp_emb[b][j0g][0];
        float4 a1 = *(const float4*)&g_cp_emb[b][j0g][4];
        float4 b0 = *(const float4*)&g_cp_emb[b][j1g][0];
        float4 b1 = *(const float4*)&g_cp_emb[b][j1g][4];
        float n0 = g_nsq[b][j0g], n1 = g_nsq[b][j1g];
        ull* row = sJ[t];
        row[0] = packx2(a0.x, b0.x); row[1] = packx2(a0.y, b0.y);
        row[2] = packx2(a0.z, b0.z); row[3] = packx2(a0.w, b0.w);
        row[4] = packx2(a1.x, b1.x); row[5] = packx2(a1.y, b1.y);
        row[6] = packx2(a1.z, b1.z); row[7] = packx2(a1.w, b1.w);
        row[8] = packx2(n0, n1);
    }

    // i-side: 2 rows per thread, broadcast-packed
    const int gi0 = i0 + t;
    const int gi1 = gi0 + 128;
    float4 ea0 = *(const float4*)&g_cp_emb[b][gi0][0];
    float4 eb0 = *(const float4*)&g_cp_emb[b][gi0][4];
    float4 ea1 = *(const float4*)&g_cp_emb[b][gi1][0];
    float4 eb1 = *(const float4*)&g_cp_emb[b][gi1][4];
    ull a0_0 = packx2(ea0.x, ea0.x), a0_1 = packx2(ea0.y, ea0.y);
    ull a0_2 = packx2(ea0.z, ea0.z), a0_3 = packx2(ea0.w, ea0.w);
    ull a0_4 = packx2(eb0.x, eb0.x), a0_5 = packx2(eb0.y, eb0.y);
    ull a0_6 = packx2(eb0.z, eb0.z), a0_7 = packx2(eb0.w, eb0.w);
    ull a1_0 = packx2(ea1.x, ea1.x), a1_1 = packx2(ea1.y, ea1.y);
    ull a1_2 = packx2(ea1.z, ea1.z), a1_3 = packx2(ea1.w, ea1.w);
    ull a1_4 = packx2(eb1.x, eb1.x), a1_5 = packx2(eb1.y, eb1.y);
    ull a1_6 = packx2(eb1.z, eb1.z), a1_7 = packx2(eb1.w, eb1.w);
    float nqs0 = (gi0 < P) ? g_nsq[b][gi0] : -3.0e38f;   // invalid -> ex2 underflow
    float nqs1 = (gi1 < P) ? g_nsq[b][gi1] : -3.0e38f;
    ull nq2_0 = packx2(nqs0, nqs0);
    ull nq2_1 = packx2(nqs1, nqs1);
    __syncthreads();

    float accA = 0.f, accB = 0.f, accC = 0.f, accD = 0.f;
    const bool clean = (tj >= 2 * ti + 2) && (jn == JT);
    if (clean) {
        #pragma unroll 4
        for (int jj = 0; jj < JT / 2; jj++) {
            const ull* row = sJ[jj];
            ulonglong2 r01 = *(const ulonglong2*)&row[0];
            ulonglong2 r23 = *(const ulonglong2*)&row[2];
            ulonglong2 r45 = *(const ulonglong2*)&row[4];
            ulonglong2 r67 = *(const ulonglong2*)&row[6];
            ull seed = row[8];
            ull ca = ffma2(a0_0, r01.x, seed);
            ca = ffma2(a0_1, r01.y, ca);
            ca = ffma2(a0_2, r23.x, ca);
            ca = ffma2(a0_3, r23.y, ca);
            ull cb = ffma2(a0_4, r45.x, nq2_0);
            cb = ffma2(a0_5, r45.y, cb);
            cb = ffma2(a0_6, r67.x, cb);
            cb = ffma2(a0_7, r67.y, cb);
            float lo, hi;
            unpackx2(lo, hi, addx2(ca, cb));
            accA += ex2f(lo);
            accB += ex2f(hi);
            ull da = ffma2(a1_0, r01.x, seed);
            da = ffma2(a1_1, r01.y, da);
            da = ffma2(a1_2, r23.x, da);
            da = ffma2(a1_3, r23.y, da);
            ull db = ffma2(a1_4, r45.x, nq2_1);
            db = ffma2(a1_5, r45.y, db);
            db = ffma2(a1_6, r67.x, db);
            db = ffma2(a1_7, r67.y, db);
            unpackx2(lo, hi, addx2(da, db));
            accC += ex2f(lo);
            accD += ex2f(hi);
        }
    } else {
        const int jn2 = (jn + 1) >> 1;
        for (int jj = 0; jj < jn2; jj++) {
            const ull* row = sJ[jj];
            ulonglong2 r01 = *(const ulonglong2*)&row[0];
            ulonglong2 r23 = *(const ulonglong2*)&row[2];
            ulonglong2 r45 = *(const ulonglong2*)&row[4];
            ulonglong2 r67 = *(const ulonglong2*)&row[6];
            ull seed = row[8];
            const int jg0 = j0 + 2 * jj;
            const int jg1 = jg0 + 1;
            ull ca = ffma2(a0_0, r01.x, seed);
            ca = ffma2(a0_1, r01.y, ca);
            ca = ffma2(a0_2, r23.x, ca);
            ca = ffma2(a0_3, r23.y, ca);
            ull cb = ffma2(a0_4, r45.x, nq2_0);
            cb = ffma2(a0_5, r45.y, cb);
            cb = ffma2(a0_6, r67.x, cb);
            cb = ffma2(a0_7, r67.y, cb);
            float lo, hi;
            unpackx2(lo, hi, addx2(ca, cb));
            accA += (jg0 > gi0 && jg0 < P) ? ex2f(lo) : 0.f;   // strict upper triangle
            accB += (jg1 > gi0 && jg1 < P) ? ex2f(hi) : 0.f;
            ull da = ffma2(a1_0, r01.x, seed);
            da = ffma2(a1_1, r01.y, da);
            da = ffma2(a1_2, r23.x, da);
            da = ffma2(a1_3, r23.y, da);
            ull db = ffma2(a1_4, r45.x, nq2_1);
            db = ffma2(a1_5, r45.y, db);
            db = ffma2(a1_6, r67.x, db);
            db = ffma2(a1_7, r67.y, db);
            unpackx2(lo, hi, addx2(da, db));
            accC += (jg0 > gi1 && jg0 < P) ? ex2f(lo) : 0.f;
            accD += (jg1 > gi1 && jg1 < P) ? ex2f(hi) : 0.f;
        }
    }

    // warp reduce -> block reduce -> ONE scattered atomic per block
    float acc = (accA + accB) + (accC + accD);
    #pragma unroll
    for (int off = 16; off; off >>= 1)
        acc += __shfl_down_sync(0xffffffffu, acc, off);
    if (lane == 0) s_wsum[t >> 5] = acc;
    __syncthreads();
    if (t == 0) {
        float bsum = (s_wsum[0] + s_wsum[1]) + (s_wsum[2] + s_wsum[3]);
        atomicAdd(&g_rep_parts[b][(blockIdx.x * 5 + blockIdx.y) & (SLOTS - 1)], bsum);
    }
}

// ============ kernel 4: parallel finalize + counter reset ============
__global__ void __launch_bounds__(TR) k_final(float* __restrict__ out)
{
    const int t    = threadIdx.x;
    const int lane = t & 31;
    const int b    = t >> 5;       // warp per batch

    __shared__ float sred[8];

    // parallel loads: lane handles segments lane and lane+32 (all LDGs concurrent)
    const int k0 = lane, k1 = lane + 32;
    int   m0 = g_firstmax[b][k0], m1 = g_firstmax[b][k1];
    int   c0 = g_cnt[b][k0],      c1 = g_cnt[b][k1];
    float s0 = g_seg[b][k0],      s1 = g_seg[b][k1];
    float rp = g_rep_parts[b][lane] + g_rep_parts[b][lane + 32];
    const int P = g_pos[b];

    float attr = ((m0 > 0 && c0 > 0) ? s0 / fmaxf((float)c0, 1.f) : 0.f)
               + ((m1 > 0 && c1 > 0) ? s1 / fmaxf((float)c1, 1.f) : 0.f);

    #pragma unroll
    for (int off = 16; off; off >>= 1) {
        attr += __shfl_down_sync(0xffffffffu, attr, off);
        rp   += __shfl_down_sync(0xffffffffu, rp,   off);
    }
    if (lane == 0) {
        float pos = (float)P;
        float neg = (float)NN - pos;
        int   valid = (pos >= 1.f) && (neg >= 1.f);
        float pw  = neg / (pos + 1e-6f);
        float bce = (pw * g_bce1[b] + g_bce0[b]) / (float)NN;
        float rep_sum = pos + 2.f * rp;                // diagonal = pos exactly
        float rep = (pos > 1.f) ? rep_sum / fmaxf(pos * pos, 1.f) : 0.f;
        sred[b]     = valid ? (bce + attr + rep) : 0.f;
        sred[4 + b] = valid ? 1.f : 0.f;
    }
    __syncthreads();
    if (t == 0) {
        float ts = 0.f, cnt = 0.f;
        #pragma unroll
        for (int bb = 0; bb < BB; bb++) { ts += sred[bb]; cnt += sred[4 + bb]; }
        out[0] = (cnt > 0.f) ? ts / fmaxf(cnt, 1.f) : 0.f;
    }
    // reset accumulators for the next graph replay (parallel stores)
    for (int idx = t; idx < BB * KK; idx += TR) {
        int bb = idx >> 6, k = idx & 63;
        g_cnt[bb][k]       = 0;
        g_firstmax[bb][k]  = 0;
        g_seg[bb][k]       = 0.f;
        g_rep_parts[bb][k] = 0.f;     // KK == SLOTS
    }
    if (t < BB) {
        g_pos[t]  = 0;
        g_bce1[t] = 0.f;
        g_bce0[t] = 0.f;
    }
}

// ================= launch =================
extern "C" void kernel_launch(void* const* d_in, const int* in_sizes, int n_in,
                              void* d_out, int out_size)
{
    const float* beta  = (const float*)d_in[0];
    const float* embed = (const float*)d_in[1];
    const int*   sid   = (const int*)  d_in[2];
    const int*   iscp  = (const int*)  d_in[3];
    float* out = (float*)d_out;

    dim3 g1(CC1, BB);
    k_pass1<<<g1, CH1>>>(beta, embed, sid, iscp);
    dim3 g2(CC2, BB);
    k_pass2<<<g2, CH2>>>(embed, sid);
    dim3 g3(GI, GJ, BB);
    k_rep<<<g3, TR>>>();
    k_final<<<1, TR>>>(out);
}